// round 1
// baseline (speedup 1.0000x reference)
#include <cuda_runtime.h>

#define NB      65536
#define N_CONT  6
#define N_CAT   6
#define NCATG   100
#define QF      12
#define DD      10
#define HID     20
#define L1N     30
#define L2N     20
#define NP      78

#define THREADS 128

// ---- shared memory layout (offsets in floats) ----
#define OFF_WA   0              // [10][32]  sW1 rows 0..9  (A projection)
#define OFF_WB   320            // [10][32]  sW1 rows 10..19 (B projection)
#define OFF_C1   640            // [78][32]  per-pair token bias: tok_p@sW1[20:30]+sb1
#define OFF_W2   3136           // [30][20]
#define OFF_W3   3736           // [20]
#define OFF_SB2  3756           // [20]
#define OFF_CW1  3776           // [6][20]
#define OFF_CB1  3896           // [6][20]
#define OFF_CW2  4016           // [6][20][12] (d padded 10->12)
#define OFF_CB2  5456           // [6][12]
#define OFF_OUTW 5528           // [80]
#define OFF_MISC 5608           // [0]=sb3, [1]=out_b
#define OFF_E    5612           // per-thread E: [THREADS][148]
#define E_STRIDE 148            // 12 slots of 12 floats + 4 pad (conflict-free v4)
#define SMEM_FLOATS (OFF_E + THREADS * E_STRIDE)

extern __shared__ float smem[];

__global__ void __launch_bounds__(THREADS, 2)
pin_kernel(const float* __restrict__ x_cont, const int* __restrict__ x_cat,
           const float* __restrict__ exposure,
           const float* __restrict__ cont_W1, const float* __restrict__ cont_b1,
           const float* __restrict__ cont_W2, const float* __restrict__ cont_b2,
           const float* __restrict__ cat_tables, const float* __restrict__ tokens,
           const float* __restrict__ sW1, const float* __restrict__ sb1,
           const float* __restrict__ sW2, const float* __restrict__ sb2,
           const float* __restrict__ sW3, const float* __restrict__ sb3,
           const float* __restrict__ out_w, const float* __restrict__ out_b,
           float* __restrict__ out)
{
    const int tid = threadIdx.x;

    // ---------------- cooperative weight staging ----------------
    for (int i = tid; i < 300; i += THREADS) {
        int d = i / 30, l = i % 30;
        smem[OFF_WA + d * 32 + l] = sW1[i];          // rows 0..9
        smem[OFF_WB + d * 32 + l] = sW1[300 + i];    // rows 10..19
    }
    for (int i = tid; i < 600; i += THREADS) smem[OFF_W2 + i] = sW2[i];
    for (int i = tid; i < 20; i += THREADS) {
        smem[OFF_W3 + i]  = sW3[i];
        smem[OFF_SB2 + i] = sb2[i];
    }
    for (int i = tid; i < 120; i += THREADS) {
        smem[OFF_CW1 + i] = cont_W1[i];
        smem[OFF_CB1 + i] = cont_b1[i];
    }
    for (int i = tid; i < 1200; i += THREADS) {
        int c = i / 200, r = i % 200, h = r / 10, d = r % 10;
        smem[OFF_CW2 + (c * 20 + h) * 12 + d] = cont_W2[i];
    }
    for (int i = tid; i < 60; i += THREADS)
        smem[OFF_CB2 + (i / 10) * 12 + (i % 10)] = cont_b2[i];
    for (int i = tid; i < NP; i += THREADS) smem[OFF_OUTW + i] = out_w[i];
    if (tid == 0) {
        smem[OFF_MISC + 0] = sb3[0];
        smem[OFF_MISC + 1] = out_b[0];
    }
    // per-pair token bias c1[p][l] = sb1[l] + sum_d tokens[p][d] * sW1[20+d][l]
    for (int i = tid; i < NP * L1N; i += THREADS) {
        int p = i / L1N, l = i % L1N;
        float acc = sb1[l];
#pragma unroll
        for (int d = 0; d < 10; ++d)
            acc = fmaf(tokens[p * 10 + d], sW1[(20 + d) * 30 + l], acc);
        smem[OFF_C1 + p * 32 + l] = acc;
    }
    __syncthreads();

    // ---------------- per-sample work ----------------
    const int b = blockIdx.x * THREADS + tid;
    float* myE = smem + OFF_E + tid * E_STRIDE;

    // continuous-feature subnet: E[c] = relu(x*W1+b1) @ W2 + b2
    float xc[6];
#pragma unroll
    for (int c = 0; c < 6; ++c) xc[c] = x_cont[b * 6 + c];

#pragma unroll 1
    for (int c = 0; c < 6; ++c) {
        float acc[10];
#pragma unroll
        for (int d = 0; d < 10; ++d) acc[d] = smem[OFF_CB2 + c * 12 + d];
#pragma unroll
        for (int h = 0; h < 20; ++h) {
            float hv = fmaxf(fmaf(xc[c], smem[OFF_CW1 + c * 20 + h],
                                  smem[OFF_CB1 + c * 20 + h]), 0.f);
#pragma unroll
            for (int d = 0; d < 10; ++d)
                acc[d] = fmaf(hv, smem[OFF_CW2 + (c * 20 + h) * 12 + d], acc[d]);
        }
#pragma unroll
        for (int d = 0; d < 10; ++d) myE[c * 12 + d] = acc[d];
    }
    // categorical embeddings
#pragma unroll 1
    for (int c = 0; c < 6; ++c) {
        int idx = x_cat[b * 6 + c];
        const float* row = cat_tables + (size_t)(c * NCATG + idx) * 10;
#pragma unroll
        for (int d = 0; d < 10; ++d) myE[(6 + c) * 12 + d] = row[d];
    }

    // ---------------- pair loop ----------------
    float eta = 0.f;
    int p = 0;
#pragma unroll 1
    for (int j = 0; j < QF; ++j) {
        float ej[10];
        {
            const float4* ev = (const float4*)(myE + j * 12);
            float4 a0 = ev[0], a1 = ev[1];
            float2 a2 = *(const float2*)(myE + j * 12 + 8);
            ej[0]=a0.x; ej[1]=a0.y; ej[2]=a0.z; ej[3]=a0.w;
            ej[4]=a1.x; ej[5]=a1.y; ej[6]=a1.z; ej[7]=a1.w;
            ej[8]=a2.x; ej[9]=a2.y;
        }
        float A[30];
#pragma unroll
        for (int l = 0; l < 30; ++l) A[l] = 0.f;
#pragma unroll
        for (int d = 0; d < 10; ++d) {
#pragma unroll
            for (int l = 0; l < 30; ++l)
                A[l] = fmaf(ej[d], smem[OFF_WA + d * 32 + l], A[l]);
        }

#pragma unroll 1
        for (int k = j; k < QF; ++k, ++p) {
            float ek[10];
            {
                const float4* ev = (const float4*)(myE + k * 12);
                float4 a0 = ev[0], a1 = ev[1];
                float2 a2 = *(const float2*)(myE + k * 12 + 8);
                ek[0]=a0.x; ek[1]=a0.y; ek[2]=a0.z; ek[3]=a0.w;
                ek[4]=a1.x; ek[5]=a1.y; ek[6]=a1.z; ek[7]=a1.w;
                ek[8]=a2.x; ek[9]=a2.y;
            }
            float Bv[30];
#pragma unroll
            for (int l = 0; l < 30; ++l) Bv[l] = 0.f;
#pragma unroll
            for (int d = 0; d < 10; ++d) {
#pragma unroll
                for (int l = 0; l < 30; ++l)
                    Bv[l] = fmaf(ek[d], smem[OFF_WB + d * 32 + l], Bv[l]);
            }

            float h2[20];
#pragma unroll
            for (int o = 0; o < 20; ++o) h2[o] = smem[OFF_SB2 + o];
            const float* c1p = smem + OFF_C1 + p * 32;
#pragma unroll
            for (int l = 0; l < 30; ++l) {
                float h1 = fmaxf(A[l] + Bv[l] + c1p[l], 0.f);
#pragma unroll
                for (int o = 0; o < 20; ++o)
                    h2[o] = fmaf(h1, smem[OFF_W2 + l * 20 + o], h2[o]);
            }
            float raw = smem[OFF_MISC + 0];
#pragma unroll
            for (int o = 0; o < 20; ++o)
                raw = fmaf(fmaxf(h2[o], 0.f), smem[OFF_W3 + o], raw);
            // centered hard sigmoid
            float ht = fminf(fmaxf(raw * (1.f / 6.f) + 0.5f, 0.f), 1.f) - 0.5f;
            eta = fmaf(smem[OFF_OUTW + p], ht, eta);
        }
    }

    eta += smem[OFF_MISC + 1];
    eta = fminf(fmaxf(eta, -20.f), 20.f);
    out[b] = expf(eta) * exposure[b];
}

extern "C" void kernel_launch(void* const* d_in, const int* in_sizes, int n_in,
                              void* d_out, int out_size)
{
    (void)in_sizes; (void)n_in; (void)out_size;
    size_t shmem = SMEM_FLOATS * sizeof(float);
    cudaFuncSetAttribute(pin_kernel, cudaFuncAttributeMaxDynamicSharedMemorySize,
                         (int)shmem);
    pin_kernel<<<NB / THREADS, THREADS, shmem>>>(
        (const float*)d_in[0],  (const int*)d_in[1],   (const float*)d_in[2],
        (const float*)d_in[3],  (const float*)d_in[4], (const float*)d_in[5],
        (const float*)d_in[6],  (const float*)d_in[7], (const float*)d_in[8],
        (const float*)d_in[9],  (const float*)d_in[10],(const float*)d_in[11],
        (const float*)d_in[12], (const float*)d_in[13],(const float*)d_in[14],
        (const float*)d_in[15], (const float*)d_in[16],
        (float*)d_out);
}